// round 1
// baseline (speedup 1.0000x reference)
#include <cuda_runtime.h>
#include <cuda_bf16.h>

#define B_  4
#define T_  4096
#define C_  64
#define HS_ 64
#define BM  128      // query rows per block (== blockDim.x)
#define BN  16       // key tile (SMEM) size

// Scratch for projected q, k, v (fp32). 3 x 4MB. Device globals (no cudaMalloc allowed).
__device__ float g_q[B_ * T_ * HS_];
__device__ float g_k[B_ * T_ * HS_];
__device__ float g_v[B_ * T_ * HS_];

// ---------------------------------------------------------------------------
// Kernel 1: fused QKV projection.  q/k/v[b,t,h] = sum_c x[b,t,c] * W*[c,h]
// One thread per (b,t) row; W matrices staged in SMEM (broadcast reads).
// ---------------------------------------------------------------------------
__global__ __launch_bounds__(128) void qkv_proj_kernel(
    const float* __restrict__ x,
    const float* __restrict__ Wq,
    const float* __restrict__ Wk,
    const float* __restrict__ Wv)
{
    __shared__ float sWq[C_ * HS_];
    __shared__ float sWk[C_ * HS_];
    __shared__ float sWv[C_ * HS_];

    const int tid = threadIdx.x;
    for (int i = tid; i < C_ * HS_; i += 128) {
        sWq[i] = Wq[i];
        sWk[i] = Wk[i];
        sWv[i] = Wv[i];
    }
    __syncthreads();

    const int row = blockIdx.x * 128 + tid;   // over B_*T_ rows

    // Load x row into registers (vectorized).
    float xr[C_];
    const float4* xp = reinterpret_cast<const float4*>(x + (size_t)row * C_);
#pragma unroll
    for (int i = 0; i < C_ / 4; i++) {
        float4 t = xp[i];
        xr[4 * i + 0] = t.x; xr[4 * i + 1] = t.y;
        xr[4 * i + 2] = t.z; xr[4 * i + 3] = t.w;
    }

    float* qo = g_q + (size_t)row * HS_;
    float* ko = g_k + (size_t)row * HS_;
    float* vo = g_v + (size_t)row * HS_;

#pragma unroll 4
    for (int h = 0; h < HS_; h++) {
        float aq = 0.f, ak = 0.f, av = 0.f;
#pragma unroll
        for (int d = 0; d < C_; d++) {
            const float xv = xr[d];
            aq = fmaf(xv, sWq[d * HS_ + h], aq);
            ak = fmaf(xv, sWk[d * HS_ + h], ak);
            av = fmaf(xv, sWv[d * HS_ + h], av);
        }
        qo[h] = aq; ko[h] = ak; vo[h] = av;
    }
}

// ---------------------------------------------------------------------------
// Kernel 2: causal flash attention, fp32.
//   wei = (q . k) * sqrt(C) = (q . k) * 8     (reference multiplies by C**0.5)
// One thread == one query row. q row + O accumulator in registers.
// K/V tiles (BN x 64) staged in SMEM; all-lane-broadcast LDS (conflict free).
// Online softmax per BN-key tile.
// ---------------------------------------------------------------------------
__global__ __launch_bounds__(BM, 1) void attn_kernel(float* __restrict__ out)
{
    const int b   = blockIdx.y;
    const int q0  = blockIdx.x * BM;
    const int tid = threadIdx.x;
    const int qi  = q0 + tid;                 // this thread's query row

    __shared__ float sK[BN * HS_];
    __shared__ float sV[BN * HS_];

    // Load q row into registers.
    float qr[HS_];
    {
        const float4* qp = reinterpret_cast<const float4*>(
            g_q + ((size_t)b * T_ + qi) * HS_);
#pragma unroll
        for (int i = 0; i < HS_ / 4; i++) {
            float4 t = qp[i];
            qr[4 * i + 0] = t.x; qr[4 * i + 1] = t.y;
            qr[4 * i + 2] = t.z; qr[4 * i + 3] = t.w;
        }
    }

    float o[HS_];
#pragma unroll
    for (int i = 0; i < HS_; i++) o[i] = 0.f;
    float m = -1e30f;   // running max (finite sentinel: avoids inf-inf NaN)
    float l = 0.f;      // running denominator

    const int kend = q0 + BM;  // keys needed: [0, q0+BM) covers all rows' causal span

    for (int k0 = 0; k0 < kend; k0 += BN) {
        // ---- stage K/V tile (block-uniform barriers) ----
        __syncthreads();
        {
            const float4* gk = reinterpret_cast<const float4*>(
                g_k + ((size_t)b * T_ + k0) * HS_);
            const float4* gv = reinterpret_cast<const float4*>(
                g_v + ((size_t)b * T_ + k0) * HS_);
            float4* sk4 = reinterpret_cast<float4*>(sK);
            float4* sv4 = reinterpret_cast<float4*>(sV);
#pragma unroll
            for (int i = 0; i < (BN * HS_ / 4) / BM; i++) {
                const int idx = i * BM + tid;
                sk4[idx] = gk[idx];
                sv4[idx] = gv[idx];
            }
        }
        __syncthreads();

        // ---- compute (predicated so barriers stay uniform) ----
        if (k0 <= qi) {
            const int jmax = min(BN, qi - k0 + 1);  // causal bound inside tile

            // Scores for this tile. Fully unrolled -> s[] stays in registers.
            float s[BN];
            float bmax = -1e30f;
#pragma unroll
            for (int j = 0; j < BN; j++) {
                float val = -1e30f;
                if (j < jmax) {
                    float a0 = 0.f, a1 = 0.f, a2 = 0.f, a3 = 0.f;
                    const float4* kr = reinterpret_cast<const float4*>(sK + j * HS_);
#pragma unroll
                    for (int d4 = 0; d4 < HS_ / 4; d4++) {
                        float4 kv = kr[d4];
                        a0 = fmaf(qr[4 * d4 + 0], kv.x, a0);
                        a1 = fmaf(qr[4 * d4 + 1], kv.y, a1);
                        a2 = fmaf(qr[4 * d4 + 2], kv.z, a2);
                        a3 = fmaf(qr[4 * d4 + 3], kv.w, a3);
                    }
                    val = (a0 + a1 + a2 + a3) * 8.0f;   // * C**0.5
                }
                s[j] = val;
                bmax = fmaxf(bmax, val);
            }

            // Online softmax rescale.
            const float mnew = fmaxf(m, bmax);
            const float corr = __expf(m - mnew);
            l *= corr;
#pragma unroll
            for (int i = 0; i < HS_; i++) o[i] *= corr;

            // Accumulate P·V.
#pragma unroll
            for (int j = 0; j < BN; j++) {
                if (j < jmax) {
                    const float p = __expf(s[j] - mnew);
                    l += p;
                    const float4* vr = reinterpret_cast<const float4*>(sV + j * HS_);
#pragma unroll
                    for (int d4 = 0; d4 < HS_ / 4; d4++) {
                        float4 vv = vr[d4];
                        o[4 * d4 + 0] = fmaf(p, vv.x, o[4 * d4 + 0]);
                        o[4 * d4 + 1] = fmaf(p, vv.y, o[4 * d4 + 1]);
                        o[4 * d4 + 2] = fmaf(p, vv.z, o[4 * d4 + 2]);
                        o[4 * d4 + 3] = fmaf(p, vv.w, o[4 * d4 + 3]);
                    }
                }
            }
            m = mnew;
        }
    }

    // Normalize and write out.
    const float inv = 1.0f / l;
    float4* op = reinterpret_cast<float4*>(out + ((size_t)b * T_ + qi) * HS_);
#pragma unroll
    for (int i = 0; i < HS_ / 4; i++) {
        float4 t;
        t.x = o[4 * i + 0] * inv;
        t.y = o[4 * i + 1] * inv;
        t.z = o[4 * i + 2] * inv;
        t.w = o[4 * i + 3] * inv;
        op[i] = t;
    }
}

// ---------------------------------------------------------------------------
extern "C" void kernel_launch(void* const* d_in, const int* in_sizes, int n_in,
                              void* d_out, int out_size)
{
    const float* x  = (const float*)d_in[0];
    const float* Wq = (const float*)d_in[1];
    const float* Wk = (const float*)d_in[2];
    const float* Wv = (const float*)d_in[3];
    float* out = (float*)d_out;

    qkv_proj_kernel<<<(B_ * T_) / 128, 128>>>(x, Wq, Wk, Wv);

    dim3 grid(T_ / BM, B_);
    attn_kernel<<<grid, BM>>>(out);
}

// round 2
// speedup vs baseline: 2.0540x; 2.0540x over previous
#include <cuda_runtime.h>
#include <cuda_bf16.h>

#define B_  4
#define T_  4096
#define C_  64
#define HS_ 64
#define BM  128      // query rows per tile
#define BN  16       // key tile (SMEM) size
#define NT  (T_ / BM)   // 32 q-tiles per batch
#define KC  512      // keys per split-K chunk
#define NCMAX 8      // max chunks per q-tile (tile 31: 4096/512)

// Scratch (device globals — no cudaMalloc allowed).
__device__ float g_q[B_ * T_ * HS_];
__device__ float g_k[B_ * T_ * HS_];
__device__ float g_v[B_ * T_ * HS_];
// Split-K partials: per (b, row, chunk): m, l, o[64]
__device__ float g_pm[B_ * T_ * NCMAX];
__device__ float g_pl[B_ * T_ * NCMAX];
__device__ float g_po[(size_t)B_ * T_ * NCMAX * HS_];

// ---------------------------------------------------------------------------
// Kernel 1: fused QKV projection.
// ---------------------------------------------------------------------------
__global__ __launch_bounds__(128) void qkv_proj_kernel(
    const float* __restrict__ x,
    const float* __restrict__ Wq,
    const float* __restrict__ Wk,
    const float* __restrict__ Wv)
{
    __shared__ float sWq[C_ * HS_];
    __shared__ float sWk[C_ * HS_];
    __shared__ float sWv[C_ * HS_];

    const int tid = threadIdx.x;
    for (int i = tid; i < C_ * HS_; i += 128) {
        sWq[i] = Wq[i];
        sWk[i] = Wk[i];
        sWv[i] = Wv[i];
    }
    __syncthreads();

    const int row = blockIdx.x * 128 + tid;

    float xr[C_];
    const float4* xp = reinterpret_cast<const float4*>(x + (size_t)row * C_);
#pragma unroll
    for (int i = 0; i < C_ / 4; i++) {
        float4 t = xp[i];
        xr[4 * i + 0] = t.x; xr[4 * i + 1] = t.y;
        xr[4 * i + 2] = t.z; xr[4 * i + 3] = t.w;
    }

    float* qo = g_q + (size_t)row * HS_;
    float* ko = g_k + (size_t)row * HS_;
    float* vo = g_v + (size_t)row * HS_;

#pragma unroll 4
    for (int h = 0; h < HS_; h++) {
        float aq = 0.f, ak = 0.f, av = 0.f;
#pragma unroll
        for (int d = 0; d < C_; d++) {
            const float xv = xr[d];
            aq = fmaf(xv, sWq[d * HS_ + h], aq);
            ak = fmaf(xv, sWk[d * HS_ + h], ak);
            av = fmaf(xv, sWv[d * HS_ + h], av);
        }
        qo[h] = aq; ko[h] = ak; vo[h] = av;
    }
}

// ---------------------------------------------------------------------------
// Kernel 2: split-K causal flash attention partials.
// Block = 256 threads: 128 query rows x 2 head-dim halves.
// blockIdx.x in [0,144) maps (heavy-first) to (q-tile t, key-chunk c).
// Each block computes partial (m, l, o) over keys [c*KC, min((c+1)*KC, span)).
// ---------------------------------------------------------------------------
__global__ __launch_bounds__(256, 2) void attn_partial_kernel()
{
    const int b = blockIdx.y;

    // Map flat index -> (t, c), heaviest tiles first.
    int u = blockIdx.x, t = 0, c = 0;
#pragma unroll 1
    for (int tt = NT - 1; tt >= 0; tt--) {
        const int n = tt / 4 + 1;           // ceil((tt+1)*BM / KC)
        if (u < n) { t = tt; c = u; break; }
        u -= n;
    }

    const int q0   = t * BM;
    const int tid  = threadIdx.x;
    const int r    = tid >> 1;              // row within tile
    const int half = tid & 1;               // head-dim half
    const int qi   = q0 + r;
    const int k0c  = c * KC;
    const int kend = min(k0c + KC, (t + 1) * BM);

    __shared__ float sK[BN * HS_];
    __shared__ float sV[BN * HS_];

    // Load this thread's half of the q row.
    float qr[32];
    {
        const float4* qp = reinterpret_cast<const float4*>(
            g_q + ((size_t)b * T_ + qi) * HS_ + half * 32);
#pragma unroll
        for (int i = 0; i < 8; i++) {
            float4 v = qp[i];
            qr[4 * i + 0] = v.x; qr[4 * i + 1] = v.y;
            qr[4 * i + 2] = v.z; qr[4 * i + 3] = v.w;
        }
    }

    float o[32];
#pragma unroll
    for (int i = 0; i < 32; i++) o[i] = 0.f;
    float m = -1e30f;
    float l = 0.f;

    for (int k0 = k0c; k0 < kend; k0 += BN) {
        __syncthreads();
        // Stage K/V tile: 256 float4 each, one per thread.
        {
            const float4* gk = reinterpret_cast<const float4*>(
                g_k + ((size_t)b * T_ + k0) * HS_);
            const float4* gv = reinterpret_cast<const float4*>(
                g_v + ((size_t)b * T_ + k0) * HS_);
            reinterpret_cast<float4*>(sK)[tid] = gk[tid];
            reinterpret_cast<float4*>(sV)[tid] = gv[tid];
        }
        __syncthreads();

        // Warp-uniform skip: k0 and warp row-base are both multiples of 16.
        if (k0 <= qi) {
            const int jmax = min(BN, qi - k0 + 1);

            float s[BN];
            float bmax = -1e30f;
#pragma unroll
            for (int j = 0; j < BN; j++) {
                float a0 = 0.f, a1 = 0.f, a2 = 0.f, a3 = 0.f;
                const float4* kr = reinterpret_cast<const float4*>(
                    sK + j * HS_ + half * 32);
#pragma unroll
                for (int d4 = 0; d4 < 8; d4++) {
                    float4 kv = kr[d4];
                    a0 = fmaf(qr[4 * d4 + 0], kv.x, a0);
                    a1 = fmaf(qr[4 * d4 + 1], kv.y, a1);
                    a2 = fmaf(qr[4 * d4 + 2], kv.z, a2);
                    a3 = fmaf(qr[4 * d4 + 3], kv.w, a3);
                }
                float a = (a0 + a1) + (a2 + a3);
                a += __shfl_xor_sync(0xFFFFFFFFu, a, 1);   // combine halves
                s[j] = (j < jmax) ? a * 8.0f : -1e30f;     // * C**0.5, masked
                bmax = fmaxf(bmax, s[j]);
            }

            const float mnew = fmaxf(m, bmax);
            const float corr = __expf(m - mnew);
            l *= corr;
#pragma unroll
            for (int i = 0; i < 32; i++) o[i] *= corr;

#pragma unroll
            for (int j = 0; j < BN; j++) {
                const float p = __expf(s[j] - mnew);       // 0 for masked j
                l += p;
                const float4* vr = reinterpret_cast<const float4*>(
                    sV + j * HS_ + half * 32);
#pragma unroll
                for (int d4 = 0; d4 < 8; d4++) {
                    float4 vv = vr[d4];
                    o[4 * d4 + 0] = fmaf(p, vv.x, o[4 * d4 + 0]);
                    o[4 * d4 + 1] = fmaf(p, vv.y, o[4 * d4 + 1]);
                    o[4 * d4 + 2] = fmaf(p, vv.z, o[4 * d4 + 2]);
                    o[4 * d4 + 3] = fmaf(p, vv.w, o[4 * d4 + 3]);
                }
            }
            m = mnew;
        }
    }

    // Write partials.
    const size_t pidx = ((size_t)b * T_ + qi) * NCMAX + c;
    if (half == 0) {
        g_pm[pidx] = m;
        g_pl[pidx] = l;
    }
    float4* pp = reinterpret_cast<float4*>(g_po + pidx * HS_ + half * 32);
#pragma unroll
    for (int i = 0; i < 8; i++) {
        float4 v;
        v.x = o[4 * i + 0]; v.y = o[4 * i + 1];
        v.z = o[4 * i + 2]; v.w = o[4 * i + 3];
        pp[i] = v;
    }
}

// ---------------------------------------------------------------------------
// Kernel 3: merge split-K partials. One thread per (b, row).
// ---------------------------------------------------------------------------
__global__ __launch_bounds__(128) void attn_reduce_kernel(float* __restrict__ out)
{
    const int gid = blockIdx.x * 128 + threadIdx.x;   // over B_*T_
    const int qi  = gid & (T_ - 1);
    const int t   = qi >> 7;                          // q-tile
    const int nc  = t / 4 + 1;                        // chunks for this tile
    const size_t pbase = (size_t)gid * NCMAX;

    float m = -1e30f;
    for (int cc = 0; cc < nc; cc++) m = fmaxf(m, g_pm[pbase + cc]);

    float l = 0.f;
    float o[HS_];
#pragma unroll
    for (int i = 0; i < HS_; i++) o[i] = 0.f;

    for (int cc = 0; cc < nc; cc++) {
        const float w = __expf(g_pm[pbase + cc] - m);
        l = fmaf(g_pl[pbase + cc], w, l);
        const float4* pp = reinterpret_cast<const float4*>(
            g_po + (pbase + cc) * HS_);
#pragma unroll
        for (int i = 0; i < HS_ / 4; i++) {
            float4 v = pp[i];
            o[4 * i + 0] = fmaf(w, v.x, o[4 * i + 0]);
            o[4 * i + 1] = fmaf(w, v.y, o[4 * i + 1]);
            o[4 * i + 2] = fmaf(w, v.z, o[4 * i + 2]);
            o[4 * i + 3] = fmaf(w, v.w, o[4 * i + 3]);
        }
    }

    const float inv = 1.0f / l;
    float4* op = reinterpret_cast<float4*>(out + (size_t)gid * HS_);
#pragma unroll
    for (int i = 0; i < HS_ / 4; i++) {
        float4 v;
        v.x = o[4 * i + 0] * inv;
        v.y = o[4 * i + 1] * inv;
        v.z = o[4 * i + 2] * inv;
        v.w = o[4 * i + 3] * inv;
        op[i] = v;
    }
}

// ---------------------------------------------------------------------------
extern "C" void kernel_launch(void* const* d_in, const int* in_sizes, int n_in,
                              void* d_out, int out_size)
{
    const float* x  = (const float*)d_in[0];
    const float* Wq = (const float*)d_in[1];
    const float* Wk = (const float*)d_in[2];
    const float* Wv = (const float*)d_in[3];
    float* out = (float*)d_out;

    qkv_proj_kernel<<<(B_ * T_) / 128, 128>>>(x, Wq, Wk, Wv);

    // 144 = sum over 32 tiles of ceil((t+1)*128 / 512) chunks
    dim3 pgrid(144, B_);
    attn_partial_kernel<<<pgrid, 256>>>();

    attn_reduce_kernel<<<(B_ * T_) / 128, 128>>>(out);
}

// round 3
// speedup vs baseline: 2.0596x; 1.0027x over previous
#include <cuda_runtime.h>
#include <cuda_bf16.h>

#define B_  4
#define T_  4096
#define C_  64
#define HS_ 64
#define BM  128      // query rows per tile
#define BN  16       // key tile (SMEM) size
#define NT  (T_ / BM)   // 32 q-tiles per batch
#define KC  512      // keys per split-K chunk
#define NCMAX 8      // max chunks per q-tile (tile 31: 4096/512)

// Scratch (device globals — no cudaMalloc allowed).
__device__ float g_q[B_ * T_ * HS_];
__device__ float g_k[B_ * T_ * HS_];
__device__ float g_v[B_ * T_ * HS_];
// Split-K partials: per (b, row, chunk): m, l, o[64]
__device__ float g_pm[B_ * T_ * NCMAX];
__device__ float g_pl[B_ * T_ * NCMAX];
__device__ float g_po[(size_t)B_ * T_ * NCMAX * HS_];

// ---------------------------------------------------------------------------
// Kernel 1: fused QKV projection.
// ---------------------------------------------------------------------------
__global__ __launch_bounds__(128) void qkv_proj_kernel(
    const float* __restrict__ x,
    const float* __restrict__ Wq,
    const float* __restrict__ Wk,
    const float* __restrict__ Wv)
{
    __shared__ float sWq[C_ * HS_];
    __shared__ float sWk[C_ * HS_];
    __shared__ float sWv[C_ * HS_];

    const int tid = threadIdx.x;
    for (int i = tid; i < C_ * HS_; i += 128) {
        sWq[i] = Wq[i];
        sWk[i] = Wk[i];
        sWv[i] = Wv[i];
    }
    __syncthreads();

    const int row = blockIdx.x * 128 + tid;

    float xr[C_];
    const float4* xp = reinterpret_cast<const float4*>(x + (size_t)row * C_);
#pragma unroll
    for (int i = 0; i < C_ / 4; i++) {
        float4 t = xp[i];
        xr[4 * i + 0] = t.x; xr[4 * i + 1] = t.y;
        xr[4 * i + 2] = t.z; xr[4 * i + 3] = t.w;
    }

    float* qo = g_q + (size_t)row * HS_;
    float* ko = g_k + (size_t)row * HS_;
    float* vo = g_v + (size_t)row * HS_;

#pragma unroll 4
    for (int h = 0; h < HS_; h++) {
        float aq = 0.f, ak = 0.f, av = 0.f;
#pragma unroll
        for (int d = 0; d < C_; d++) {
            const float xv = xr[d];
            aq = fmaf(xv, sWq[d * HS_ + h], aq);
            ak = fmaf(xv, sWk[d * HS_ + h], ak);
            av = fmaf(xv, sWv[d * HS_ + h], av);
        }
        qo[h] = aq; ko[h] = ak; vo[h] = av;
    }
}

// ---------------------------------------------------------------------------
// Kernel 2: split-K causal flash attention partials.
// Block = 256 threads: 128 query rows x 2 head-dim halves.
// blockIdx.x in [0,144) maps (heavy-first) to (q-tile t, key-chunk c).
// Each block computes partial (m, l, o) over keys [c*KC, min((c+1)*KC, span)).
// ---------------------------------------------------------------------------
__global__ __launch_bounds__(256, 2) void attn_partial_kernel()
{
    const int b = blockIdx.y;

    // Map flat index -> (t, c), heaviest tiles first.
    int u = blockIdx.x, t = 0, c = 0;
#pragma unroll 1
    for (int tt = NT - 1; tt >= 0; tt--) {
        const int n = tt / 4 + 1;           // ceil((tt+1)*BM / KC)
        if (u < n) { t = tt; c = u; break; }
        u -= n;
    }

    const int q0   = t * BM;
    const int tid  = threadIdx.x;
    const int r    = tid >> 1;              // row within tile
    const int half = tid & 1;               // head-dim half
    const int qi   = q0 + r;
    const int k0c  = c * KC;
    const int kend = min(k0c + KC, (t + 1) * BM);

    __shared__ float sK[BN * HS_];
    __shared__ float sV[BN * HS_];

    // Load this thread's half of the q row.
    float qr[32];
    {
        const float4* qp = reinterpret_cast<const float4*>(
            g_q + ((size_t)b * T_ + qi) * HS_ + half * 32);
#pragma unroll
        for (int i = 0; i < 8; i++) {
            float4 v = qp[i];
            qr[4 * i + 0] = v.x; qr[4 * i + 1] = v.y;
            qr[4 * i + 2] = v.z; qr[4 * i + 3] = v.w;
        }
    }

    float o[32];
#pragma unroll
    for (int i = 0; i < 32; i++) o[i] = 0.f;
    float m = -1e30f;
    float l = 0.f;

    for (int k0 = k0c; k0 < kend; k0 += BN) {
        __syncthreads();
        // Stage K/V tile: 256 float4 each, one per thread.
        {
            const float4* gk = reinterpret_cast<const float4*>(
                g_k + ((size_t)b * T_ + k0) * HS_);
            const float4* gv = reinterpret_cast<const float4*>(
                g_v + ((size_t)b * T_ + k0) * HS_);
            reinterpret_cast<float4*>(sK)[tid] = gk[tid];
            reinterpret_cast<float4*>(sV)[tid] = gv[tid];
        }
        __syncthreads();

        // Warp-uniform skip: k0 and warp row-base are both multiples of 16.
        if (k0 <= qi) {
            const int jmax = min(BN, qi - k0 + 1);

            float s[BN];
            float bmax = -1e30f;
#pragma unroll
            for (int j = 0; j < BN; j++) {
                float a0 = 0.f, a1 = 0.f, a2 = 0.f, a3 = 0.f;
                const float4* kr = reinterpret_cast<const float4*>(
                    sK + j * HS_ + half * 32);
#pragma unroll
                for (int d4 = 0; d4 < 8; d4++) {
                    float4 kv = kr[d4];
                    a0 = fmaf(qr[4 * d4 + 0], kv.x, a0);
                    a1 = fmaf(qr[4 * d4 + 1], kv.y, a1);
                    a2 = fmaf(qr[4 * d4 + 2], kv.z, a2);
                    a3 = fmaf(qr[4 * d4 + 3], kv.w, a3);
                }
                float a = (a0 + a1) + (a2 + a3);
                a += __shfl_xor_sync(0xFFFFFFFFu, a, 1);   // combine halves
                s[j] = (j < jmax) ? a * 8.0f : -1e30f;     // * C**0.5, masked
                bmax = fmaxf(bmax, s[j]);
            }

            const float mnew = fmaxf(m, bmax);
            const float corr = __expf(m - mnew);
            l *= corr;
#pragma unroll
            for (int i = 0; i < 32; i++) o[i] *= corr;

#pragma unroll
            for (int j = 0; j < BN; j++) {
                const float p = __expf(s[j] - mnew);       // 0 for masked j
                l += p;
                const float4* vr = reinterpret_cast<const float4*>(
                    sV + j * HS_ + half * 32);
#pragma unroll
                for (int d4 = 0; d4 < 8; d4++) {
                    float4 vv = vr[d4];
                    o[4 * d4 + 0] = fmaf(p, vv.x, o[4 * d4 + 0]);
                    o[4 * d4 + 1] = fmaf(p, vv.y, o[4 * d4 + 1]);
                    o[4 * d4 + 2] = fmaf(p, vv.z, o[4 * d4 + 2]);
                    o[4 * d4 + 3] = fmaf(p, vv.w, o[4 * d4 + 3]);
                }
            }
            m = mnew;
        }
    }

    // Write partials.
    const size_t pidx = ((size_t)b * T_ + qi) * NCMAX + c;
    if (half == 0) {
        g_pm[pidx] = m;
        g_pl[pidx] = l;
    }
    float4* pp = reinterpret_cast<float4*>(g_po + pidx * HS_ + half * 32);
#pragma unroll
    for (int i = 0; i < 8; i++) {
        float4 v;
        v.x = o[4 * i + 0]; v.y = o[4 * i + 1];
        v.z = o[4 * i + 2]; v.w = o[4 * i + 3];
        pp[i] = v;
    }
}

// ---------------------------------------------------------------------------
// Kernel 3: merge split-K partials. One thread per (b, row).
// ---------------------------------------------------------------------------
__global__ __launch_bounds__(128) void attn_reduce_kernel(float* __restrict__ out)
{
    const int gid = blockIdx.x * 128 + threadIdx.x;   // over B_*T_
    const int qi  = gid & (T_ - 1);
    const int t   = qi >> 7;                          // q-tile
    const int nc  = t / 4 + 1;                        // chunks for this tile
    const size_t pbase = (size_t)gid * NCMAX;

    float m = -1e30f;
    for (int cc = 0; cc < nc; cc++) m = fmaxf(m, g_pm[pbase + cc]);

    float l = 0.f;
    float o[HS_];
#pragma unroll
    for (int i = 0; i < HS_; i++) o[i] = 0.f;

    for (int cc = 0; cc < nc; cc++) {
        const float w = __expf(g_pm[pbase + cc] - m);
        l = fmaf(g_pl[pbase + cc], w, l);
        const float4* pp = reinterpret_cast<const float4*>(
            g_po + (pbase + cc) * HS_);
#pragma unroll
        for (int i = 0; i < HS_ / 4; i++) {
            float4 v = pp[i];
            o[4 * i + 0] = fmaf(w, v.x, o[4 * i + 0]);
            o[4 * i + 1] = fmaf(w, v.y, o[4 * i + 1]);
            o[4 * i + 2] = fmaf(w, v.z, o[4 * i + 2]);
            o[4 * i + 3] = fmaf(w, v.w, o[4 * i + 3]);
        }
    }

    const float inv = 1.0f / l;
    float4* op = reinterpret_cast<float4*>(out + (size_t)gid * HS_);
#pragma unroll
    for (int i = 0; i < HS_ / 4; i++) {
        float4 v;
        v.x = o[4 * i + 0] * inv;
        v.y = o[4 * i + 1] * inv;
        v.z = o[4 * i + 2] * inv;
        v.w = o[4 * i + 3] * inv;
        op[i] = v;
    }
}

// ---------------------------------------------------------------------------
extern "C" void kernel_launch(void* const* d_in, const int* in_sizes, int n_in,
                              void* d_out, int out_size)
{
    const float* x  = (const float*)d_in[0];
    const float* Wq = (const float*)d_in[1];
    const float* Wk = (const float*)d_in[2];
    const float* Wv = (const float*)d_in[3];
    float* out = (float*)d_out;

    qkv_proj_kernel<<<(B_ * T_) / 128, 128>>>(x, Wq, Wk, Wv);

    // 144 = sum over 32 tiles of ceil((t+1)*128 / 512) chunks
    dim3 pgrid(144, B_);
    attn_partial_kernel<<<pgrid, 256>>>();

    attn_reduce_kernel<<<(B_ * T_) / 128, 128>>>(out);
}